// round 8
// baseline (speedup 1.0000x reference)
#include <cuda_runtime.h>
#include <cuda_bf16.h>
#include <cstdint>

#define Bn 16
#define Cn 64
#define Hn 160
#define Wn 160
#define HP 161
#define NLOG 9
#define NPIX (Bn * HP * HP)        // 414736 = 16 * 25921
#define NTILES (NPIX / 16)         // 25921 full 16-pixel warp tiles
#define NCONV 888                  // 148 * 6 persistent conv blocks
#define NTHR 128
#define NWARPS (NCONV * 4)
#define HW (Hn * Wn)
#define WROW 136                   // bf16 elems per nrow in W smem (272B, padded)
#define LU_STRIDE 65
#define SMEM_BYTES (64 * WROW * 2) // 17408 ; fp32 LU needs 16640 (fits)

__device__ double g_dlog[NLOG];
__device__ int    g_count = 0;

__device__ __forceinline__ void mma_bf16(float* d, const uint32_t* a, uint32_t b0, uint32_t b1) {
    asm volatile(
        "mma.sync.aligned.m16n8k16.row.col.f32.bf16.bf16.f32 "
        "{%0,%1,%2,%3}, {%4,%5,%6,%7}, {%8,%9}, {%0,%1,%2,%3};"
        : "+f"(d[0]), "+f"(d[1]), "+f"(d[2]), "+f"(d[3])
        : "r"(a[0]), "r"(a[1]), "r"(a[2]), "r"(a[3]), "r"(b0), "r"(b1));
}
__device__ __forceinline__ uint32_t pack_bf16x2(float hi, float lo) {
    uint32_t r;
    asm("cvt.rn.bf16x2.f32 %0, %1, %2;" : "=r"(r) : "f"(hi), "f"(lo));
    return r;
}

// ---- blocks 0..8: one fp32 LU each (log in fp64); last finisher writes logdet ----
__device__ void logdet_block(int r, const float* __restrict__ wgt,
                             const float* __restrict__ ldin,
                             float* __restrict__ outld,
                             unsigned char* smem_raw)
{
    float* A = reinterpret_cast<float*>(smem_raw);
    __shared__ float  s_val[2];
    __shared__ int    s_idx[2];
    __shared__ int    s_piv;
    __shared__ double s_acc;
    __shared__ int    s_ticket;

    const int tid = threadIdx.x;
    const int n   = (r == 0) ? 64 : (r <= 4 ? 32 : 16);
    const double pixw = (r == 0) ? (double)(Hn - 1) * (double)(Wn - 1)
                                 : (r <= 4 ? (double)(Wn - 1) : 1.0);
    auto chan = [&](int m) -> int {
        if (r == 0) return m;
        if (r <= 4) {
            const int t2[4][2] = {{2, 3}, {0, 1}, {1, 3}, {0, 2}};
            return 4 * (m >> 1) + t2[r - 1][m & 1];
        }
        const int t1[4] = {3, 2, 1, 0};
        return 4 * m + t1[r - 5];
    };

    for (int idx = tid; idx < n * n; idx += NTHR) {
        int ri = idx / n, ci = idx % n;
        A[ri * LU_STRIDE + ci] = wgt[chan(ri) * Cn + chan(ci)];
    }
    if (tid == 0) s_acc = 0.0;
    __syncthreads();

    for (int k = 0; k < n; k++) {
        float v = -1.0f;
        int vi = tid;
        if (tid >= k && tid < n) v = fabsf(A[tid * LU_STRIDE + k]);
        if (tid < 64) {
#pragma unroll
            for (int off = 16; off; off >>= 1) {
                float ov = __shfl_down_sync(0xffffffffu, v, off);
                int   oi = __shfl_down_sync(0xffffffffu, vi, off);
                if (ov > v) { v = ov; vi = oi; }
            }
            if ((tid & 31) == 0) { s_val[tid >> 5] = v; s_idx[tid >> 5] = vi; }
        }
        __syncthreads();
        if (tid == 0) {
            float bv = s_val[0]; int bi = s_idx[0];
            if (n > 32 && s_val[1] > bv) { bv = s_val[1]; bi = s_idx[1]; }
            s_piv = bi;
            s_acc += log((double)bv);
        }
        __syncthreads();
        const int piv = s_piv;
        if (piv != k && tid < n) {
            float t = A[k * LU_STRIDE + tid];
            A[k * LU_STRIDE + tid]   = A[piv * LU_STRIDE + tid];
            A[piv * LU_STRIDE + tid] = t;
        }
        __syncthreads();
        if (tid > k && tid < n) {
            float m = A[tid * LU_STRIDE + k] / A[k * LU_STRIDE + k];
            for (int c = k + 1; c < n; c++)
                A[tid * LU_STRIDE + c] -= m * A[k * LU_STRIDE + c];
        }
        __syncthreads();
    }

    if (tid == 0) {
        g_dlog[r] = s_acc * pixw;
        __threadfence();
        s_ticket = atomicAdd(&g_count, 1);
    }
    __syncthreads();
    if (s_ticket == NLOG - 1) {
        __threadfence();
        if (tid < Bn) {
            volatile double* gd = g_dlog;
            double s = 0.0;
#pragma unroll
            for (int k = 0; k < NLOG; k++) s += gd[k];
            outld[tid] = ldin[tid] + (float)s;
        }
        if (tid == 0) g_count = 0;
    }
}

// ---- main: warp-autonomous tiles; per-kt staged gather; LDS.128 B fragments ----
extern "C" __global__ void __launch_bounds__(NTHR)
ic1x1_kernel(const float* __restrict__ x, const float* __restrict__ wgt,
             const float* __restrict__ ldin,
             float* __restrict__ out, float* __restrict__ outld)
{
    extern __shared__ __align__(16) unsigned char smem_raw[];

    const int bx  = blockIdx.x;
    const int tid = threadIdx.x;
    if (bx < NLOG) { logdet_block(bx, wgt, ldin, outld, smem_raw); return; }

    __nv_bfloat16* wsm = reinterpret_cast<__nv_bfloat16*>(smem_raw);

    // ---- build W fragment quartets: per (nrow, kt, q2): 16B = {hi k0,k0+1,k0+8,k0+9 | lo same} ----
    for (int g = tid; g < 64 * 16; g += NTHR) {
        const int nrow = g >> 4;
        const int kt   = (g >> 2) & 3;
        const int q2   = g & 3;
        const int k0   = kt * 16 + 2 * q2;
        const float* wr = wgt + nrow * 64;
        float w0 = wr[k0], w1 = wr[k0 + 1], w2 = wr[k0 + 8], w3 = wr[k0 + 9];
        float h0 = __bfloat162float(__float2bfloat16_rn(w0));
        float h1 = __bfloat162float(__float2bfloat16_rn(w1));
        float h2 = __bfloat162float(__float2bfloat16_rn(w2));
        float h3 = __bfloat162float(__float2bfloat16_rn(w3));
        uint4 v;
        v.x = pack_bf16x2(h1, h0);
        v.y = pack_bf16x2(h3, h2);
        v.z = pack_bf16x2(w1 - h1, w0 - h0);
        v.w = pack_bf16x2(w3 - h3, w2 - h2);
        *reinterpret_cast<uint4*>(&wsm[nrow * WROW + (kt * 4 + q2) * 8]) = v;
    }
    __syncthreads();

    const int lane = tid & 31;
    const int frow = lane >> 2;      // 0..7
    const int q2   = lane & 3;
    const int fkq  = q2 << 1;
    const int pp   = 1 - (q2 & 1);   // fixed per thread
    const int scb  = (q2 >> 1) * 4 + pp * 2;   // channel base at h=0

    const uint32_t* wsm32 = reinterpret_cast<const uint32_t*>(wsm);

    const int wg = (bx - NLOG) * 4 + (tid >> 5);

    for (int t = wg; t < NTILES; t += NWARPS) {
        // ---- decode this thread's two pixels ----
        const int pidA = t * 16 + frow;
        const int pidB = pidA + 8;
        int bbA = pidA / (HP * HP); int rA = pidA - bbA * HP * HP;
        int iiA = rA / HP;          int jjA = rA - iiA * HP;
        int bbB = pidB / (HP * HP); int rB = pidB - bbB * HP * HP;
        int iiB = rB / HP;          int jjB = rB - iiB * HP;

        // fixed bases + predicates (h-stride is constant 8*HW)
        const int siA = iiA - pp, siB = iiB - pp;
        const bool rokA = (unsigned)siA < (unsigned)Hn;
        const bool rokB = (unsigned)siB < (unsigned)Hn;
        const bool ok0A = rokA && (unsigned)(jjA - 1) < (unsigned)Wn;
        const bool ok1A = rokA && jjA < Wn;
        const bool ok0B = rokB && (unsigned)(jjB - 1) < (unsigned)Wn;
        const bool ok1B = rokB && jjB < Wn;
        const float* b0A = x + (size_t)bbA * (Cn * HW) + ((scb + 1) * Hn + siA) * Wn + (jjA - 1);
        const float* b1A = x + (size_t)bbA * (Cn * HW) + (scb * Hn + siA) * Wn + jjA;
        const float* b0B = x + (size_t)bbB * (Cn * HW) + ((scb + 1) * Hn + siB) * Wn + (jjB - 1);
        const float* b1B = x + (size_t)bbB * (Cn * HW) + (scb * Hn + siB) * Wn + jjB;

        float d[8][4];
#pragma unroll
        for (int nt = 0; nt < 8; nt++)
#pragma unroll
            for (int r = 0; r < 4; r++) d[nt][r] = 0.0f;

        // prefetch kt=0 raw values (h=0,1)
        float rv[8];
        rv[0] = ok0A ? b0A[0]      : 0.0f;   // h=0 pixA v0
        rv[1] = ok1A ? b1A[0]      : 0.0f;   // h=0 pixA v1
        rv[2] = ok0B ? b0B[0]      : 0.0f;
        rv[3] = ok1B ? b1B[0]      : 0.0f;
        rv[4] = ok0A ? b0A[8 * HW] : 0.0f;   // h=1
        rv[5] = ok1A ? b1A[8 * HW] : 0.0f;
        rv[6] = ok0B ? b0B[8 * HW] : 0.0f;
        rv[7] = ok1B ? b1B[8 * HW] : 0.0f;

#pragma unroll
        for (int kt = 0; kt < 4; kt++) {
            // prefetch next kt's raw values before MMAs
            float nv[8];
            if (kt < 3) {
                const int o0 = (2 * kt + 2) * 8 * HW;
                const int o1 = (2 * kt + 3) * 8 * HW;
                nv[0] = ok0A ? b0A[o0] : 0.0f;
                nv[1] = ok1A ? b1A[o0] : 0.0f;
                nv[2] = ok0B ? b0B[o0] : 0.0f;
                nv[3] = ok1B ? b1B[o0] : 0.0f;
                nv[4] = ok0A ? b0A[o1] : 0.0f;
                nv[5] = ok1A ? b1A[o1] : 0.0f;
                nv[6] = ok0B ? b0B[o1] : 0.0f;
                nv[7] = ok1B ? b1B[o1] : 0.0f;
            }
            // convert current raw -> A fragments (lower half = v0/ci-even)
            uint32_t A_h[4], A_l[4];
#pragma unroll
            for (int e = 0; e < 4; e++) {         // e: [h-of-pair(0/1)][pix(0=A,1=B)] -> a-index
                const float v0 = rv[2 * e + 0];
                const float v1 = rv[2 * e + 1];
                const float h0 = __bfloat162float(__float2bfloat16_rn(v0));
                const float h1 = __bfloat162float(__float2bfloat16_rn(v1));
                // a-frag layout: a0=pixA lowk, a1=pixB lowk, a2=pixA highk, a3=pixB highk
                const int ai = (e & 1) + ((e >> 1) << 1);   // e0->a0, e1->a1, e2->a2, e3->a3
                A_h[ai] = pack_bf16x2(h1, h0);
                A_l[ai] = pack_bf16x2(v1 - h1, v0 - h0);
            }
#pragma unroll
            for (int nt = 0; nt < 8; nt++) {
                const int nrow = nt * 8 + frow;
                const uint32_t off = (uint32_t)(nrow * WROW + (kt * 4 + q2) * 8) >> 1;
                uint4 bb = *reinterpret_cast<const uint4*>(wsm32 + off);
                mma_bf16(d[nt], A_h, bb.x, bb.y);   // hh
                mma_bf16(d[nt], A_h, bb.z, bb.w);   // h*lo
                mma_bf16(d[nt], A_l, bb.x, bb.y);   // lo*h
            }
            if (kt < 3) {
#pragma unroll
                for (int e = 0; e < 8; e++) rv[e] = nv[e];
            }
        }

        // ---- scatter through inverse shift (predication == region masks) ----
        float* obA = out + (size_t)bbA * (Cn * HW);
        float* obB = out + (size_t)bbB * (Cn * HW);
#pragma unroll
        for (int nt = 0; nt < 8; nt++) {
#pragma unroll
            for (int r = 0; r < 4; r++) {
                const int c = nt * 8 + fkq + (r & 1);
                const int P = (c >> 1) & 1, Q = c & 1;
                const int dc = (c & ~3) | ((1 - P) << 1) | (1 - Q);
                const int ii = (r & 2) ? iiB : iiA;
                const int jj = (r & 2) ? jjB : jjA;
                float* ob    = (r & 2) ? obB : obA;
                const int di = ii - (1 - P);
                const int dj = jj - (1 - Q);
                if ((unsigned)di < (unsigned)Hn && (unsigned)dj < (unsigned)Wn)
                    ob[(dc * Hn + di) * Wn + dj] = d[nt][r];
            }
        }
    }
}

extern "C" void kernel_launch(void* const* d_in, const int* in_sizes, int n_in,
                              void* d_out, int out_size)
{
    const float *x = nullptr, *ld = nullptr, *w = nullptr;
    for (int k = 0; k < n_in; k++) {
        if (in_sizes[k] == Cn * Cn)      w  = (const float*)d_in[k];
        else if (in_sizes[k] == Bn)      ld = (const float*)d_in[k];
        else                             x  = (const float*)d_in[k];
    }
    float* out   = (float*)d_out;
    float* outld = out + (out_size - Bn);

    ic1x1_kernel<<<NLOG + NCONV, NTHR, SMEM_BYTES>>>(x, w, ld, out, outld);
}